// round 13
// baseline (speedup 1.0000x reference)
#include <cuda_runtime.h>
#include <math.h>

// Problem dims (fixed per reference setup_inputs)
#define TT   4
#define BBB  64
#define NNN  256
#define DIN  512
#define DOUT 512
#define MROWS (TT * BBB * NNN)        // 65536 rows total
#define M3   (BBB * NNN * DOUT)       // 8388608 elems per time step
#define RED_ROWS 256
#define RED_BLOCKS (MROWS / RED_ROWS) // 256
#define BK 16
#define NCHUNKS (DIN / BK)            // 32

// Scratch (allocation-free: __device__ globals)
__device__ float g_z[(size_t)MROWS * DOUT];
__device__ float g_psum[RED_BLOCKS * DOUT];
__device__ float g_psumsq[RED_BLOCKS * DOUT];
__device__ float g_mean[DOUT];
__device__ float g_rstd[DOUT];

// ---------------------------------------------------------------------------
// SGEMM: Z[m,o] = sum_d X[m,d] * W[o,d]
// 128x128 CTA tile, BK=16, 256 threads, 8x8/thread, double-buffered SMEM,
// 2 CTAs/SM — round-5 structure, plus a k-dependent column swizzle:
// element (row r, k) lives at As[k][(r + (k>>2)*8) & 127]. This makes the
// staging STS conflict-free (banks r0 + q0*8 cover all 32) while fragment
// LDS.128 reads stay contiguous/aligned/broadcast. Values are only
// relocated in SMEM -> FFMA chain bit-identical (k = 0..511 ascending,
// single fp32 accumulator per element).
// ---------------------------------------------------------------------------
__global__ __launch_bounds__(256, 2) void sgemm_kernel(const float* __restrict__ X,
                                                       const float* __restrict__ W) {
    __shared__ __align__(16) float As[2][BK][128];
    __shared__ __align__(16) float Bs[2][BK][128];

    const int tid = threadIdx.x;
    const int tx = tid & 15;          // column groups
    const int ty = tid >> 4;          // row groups
    const int r0 = tid >> 2;          // load row (first half)
    const int q0 = tid & 3;           // float4 index within 16-float row chunk

    // swizzled store columns (constant per thread: k>>2 == q0 for k=q0*4+u)
    const int sc0 = (r0 + q0 * 8) & 127;
    const int sc1 = (r0 + 64 + q0 * 8) & 127;

    const float* Ab = X + (size_t)blockIdx.y * 128 * DIN;
    const float* Wb = W + (size_t)blockIdx.x * 128 * DIN;

    float acc[8][8];
#pragma unroll
    for (int i = 0; i < 8; i++)
#pragma unroll
        for (int j = 0; j < 8; j++) acc[i][j] = 0.f;

    float4 ra0, ra1, rb0, rb1;   // staging regs for the in-flight chunk

    // --- prologue: chunk 0 -> buf 0
    ra0 = *reinterpret_cast<const float4*>(Ab + (size_t)r0 * DIN + q0 * 4);
    ra1 = *reinterpret_cast<const float4*>(Ab + (size_t)(r0 + 64) * DIN + q0 * 4);
    rb0 = *reinterpret_cast<const float4*>(Wb + (size_t)r0 * DIN + q0 * 4);
    rb1 = *reinterpret_cast<const float4*>(Wb + (size_t)(r0 + 64) * DIN + q0 * 4);
    {
        float a0[4] = {ra0.x, ra0.y, ra0.z, ra0.w};
        float a1[4] = {ra1.x, ra1.y, ra1.z, ra1.w};
        float b0[4] = {rb0.x, rb0.y, rb0.z, rb0.w};
        float b1[4] = {rb1.x, rb1.y, rb1.z, rb1.w};
#pragma unroll
        for (int u = 0; u < 4; u++) {
            As[0][q0 * 4 + u][sc0] = a0[u];
            As[0][q0 * 4 + u][sc1] = a1[u];
            Bs[0][q0 * 4 + u][sc0] = b0[u];
            Bs[0][q0 * 4 + u][sc1] = b1[u];
        }
    }
    __syncthreads();

    // LDG chunk 1
    ra0 = *reinterpret_cast<const float4*>(Ab + (size_t)r0 * DIN + BK + q0 * 4);
    ra1 = *reinterpret_cast<const float4*>(Ab + (size_t)(r0 + 64) * DIN + BK + q0 * 4);
    rb0 = *reinterpret_cast<const float4*>(Wb + (size_t)r0 * DIN + BK + q0 * 4);
    rb1 = *reinterpret_cast<const float4*>(Wb + (size_t)(r0 + 64) * DIN + BK + q0 * 4);

    for (int c = 0; c < NCHUNKS; c++) {
        const int cur = c & 1;
        // STS chunk c+1 into the other buffer (conflict-free via swizzle)
        if (c + 1 < NCHUNKS) {
            const int nxt = cur ^ 1;
            float a0[4] = {ra0.x, ra0.y, ra0.z, ra0.w};
            float a1[4] = {ra1.x, ra1.y, ra1.z, ra1.w};
            float b0[4] = {rb0.x, rb0.y, rb0.z, rb0.w};
            float b1[4] = {rb1.x, rb1.y, rb1.z, rb1.w};
#pragma unroll
            for (int u = 0; u < 4; u++) {
                As[nxt][q0 * 4 + u][sc0] = a0[u];
                As[nxt][q0 * 4 + u][sc1] = a1[u];
                Bs[nxt][q0 * 4 + u][sc0] = b0[u];
                Bs[nxt][q0 * 4 + u][sc1] = b1[u];
            }
        }
        // LDG chunk c+2 (latency hidden under this chunk's FFMAs)
        if (c + 2 < NCHUNKS) {
            const int k0 = (c + 2) * BK;
            ra0 = *reinterpret_cast<const float4*>(Ab + (size_t)r0 * DIN + k0 + q0 * 4);
            ra1 = *reinterpret_cast<const float4*>(Ab + (size_t)(r0 + 64) * DIN + k0 + q0 * 4);
            rb0 = *reinterpret_cast<const float4*>(Wb + (size_t)r0 * DIN + k0 + q0 * 4);
            rb1 = *reinterpret_cast<const float4*>(Wb + (size_t)(r0 + 64) * DIN + k0 + q0 * 4);
        }
        // Compute chunk c: k ascending (bit-identical chain per element)
#pragma unroll
        for (int kk = 0; kk < BK; kk++) {
            const int off = (kk >> 2) * 8;
            float4 a0 = *reinterpret_cast<const float4*>(&As[cur][kk][(ty * 4 + off) & 127]);
            float4 a1 = *reinterpret_cast<const float4*>(&As[cur][kk][(64 + ty * 4 + off) & 127]);
            float4 b0 = *reinterpret_cast<const float4*>(&Bs[cur][kk][(tx * 4 + off) & 127]);
            float4 b1 = *reinterpret_cast<const float4*>(&Bs[cur][kk][(64 + tx * 4 + off) & 127]);
            float ra[8] = {a0.x, a0.y, a0.z, a0.w, a1.x, a1.y, a1.z, a1.w};
            float rb[8] = {b0.x, b0.y, b0.z, b0.w, b1.x, b1.y, b1.z, b1.w};
#pragma unroll
            for (int i = 0; i < 8; i++)
#pragma unroll
                for (int j = 0; j < 8; j++) acc[i][j] += ra[i] * rb[j];
        }
        __syncthreads();
    }

    // Epilogue (same mapping as round 5)
#pragma unroll
    for (int rh = 0; rh < 2; rh++)
#pragma unroll
        for (int i = 0; i < 4; i++) {
            int row = blockIdx.y * 128 + rh * 64 + ty * 4 + i;
            float* zrow = g_z + (size_t)row * DOUT + blockIdx.x * 128;
#pragma unroll
            for (int ch = 0; ch < 2; ch++) {
                float4 v;
                v.x = acc[rh * 4 + i][ch * 4 + 0];
                v.y = acc[rh * 4 + i][ch * 4 + 1];
                v.z = acc[rh * 4 + i][ch * 4 + 2];
                v.w = acc[rh * 4 + i][ch * 4 + 3];
                *reinterpret_cast<float4*>(zrow + ch * 64 + tx * 4) = v;
            }
        }
}

// ---------------------------------------------------------------------------
// Stats: stage-1 verbatim; finalize parallel (16 CTAs x 32 thr, batched loads,
// add order b = 0..255 ascending -> bit-identical).
// ---------------------------------------------------------------------------
__global__ __launch_bounds__(256) void reduce_stats_kernel() {
    const int c = threadIdx.x;
    const size_t base = (size_t)blockIdx.x * RED_ROWS * DOUT;
    float s0 = 0.f, q0 = 0.f, s1 = 0.f, q1 = 0.f;
    for (int r = 0; r < RED_ROWS; r++) {
        float z0 = g_z[base + (size_t)r * DOUT + c];
        float z1 = g_z[base + (size_t)r * DOUT + c + 256];
        s0 += z0; q0 += z0 * z0;
        s1 += z1; q1 += z1 * z1;
    }
    g_psum  [blockIdx.x * DOUT + c]       = s0;
    g_psumsq[blockIdx.x * DOUT + c]       = q0;
    g_psum  [blockIdx.x * DOUT + c + 256] = s1;
    g_psumsq[blockIdx.x * DOUT + c + 256] = q1;
}

__global__ void finalize_stats_kernel() {
    const int o = blockIdx.x * 32 + threadIdx.x;   // one channel per thread
    float s = 0.f, q = 0.f;
    for (int b0 = 0; b0 < RED_BLOCKS; b0 += 8) {
        float sv[8], qv[8];
#pragma unroll
        for (int u = 0; u < 8; u++) {
            sv[u] = g_psum  [(b0 + u) * DOUT + o];
            qv[u] = g_psumsq[(b0 + u) * DOUT + o];
        }
#pragma unroll
        for (int u = 0; u < 8; u++) {   // add order: b ascending (bit-identical)
            s += sv[u];
            q += qv[u];
        }
    }
    const float invM = 1.0f / (float)MROWS;
    float mean = s * invM;
    float var = q * invM - mean * mean;
    g_mean[o] = mean;
    g_rstd[o] = 1.0f / sqrtf(var + 1e-5f);
}

// ---------------------------------------------------------------------------
// LIF: verbatim from the passing kernels.
// ---------------------------------------------------------------------------
__global__ __launch_bounds__(256) void lif_kernel(const float* __restrict__ gamma,
                                                  const float* __restrict__ beta,
                                                  float* __restrict__ out) {
    size_t e = ((size_t)blockIdx.x * blockDim.x + threadIdx.x) * 4;
    int o = (int)(e & (DOUT - 1));

    float4 mn4 = *reinterpret_cast<const float4*>(g_mean + o);
    float4 rs4 = *reinterpret_cast<const float4*>(g_rstd + o);
    float4 gm4 = *reinterpret_cast<const float4*>(gamma + o);
    float4 bt4 = *reinterpret_cast<const float4*>(beta + o);
    float mn[4] = {mn4.x, mn4.y, mn4.z, mn4.w};
    float rs[4] = {rs4.x, rs4.y, rs4.z, rs4.w};
    float gm[4] = {gm4.x, gm4.y, gm4.z, gm4.w};
    float bt[4] = {bt4.x, bt4.y, bt4.z, bt4.w};

    float v[4] = {0.f, 0.f, 0.f, 0.f};
#pragma unroll
    for (int t = 0; t < TT; t++) {
        float4 z4 = *reinterpret_cast<const float4*>(g_z + (size_t)t * M3 + e);
        float z[4] = {z4.x, z4.y, z4.z, z4.w};
        float s[4];
#pragma unroll
        for (int l = 0; l < 4; l++) {
            float zn = __fadd_rn(__fmul_rn(__fmul_rn(__fsub_rn(z[l], mn[l]), rs[l]), gm[l]), bt[l]);
            v[l] = __fadd_rn(v[l], __fmul_rn(__fsub_rn(zn, v[l]), 0.5f));
            bool fire = (v[l] >= 1.0f);
            s[l] = fire ? 1.0f : 0.0f;
            v[l] = fire ? 0.0f : v[l];
        }
        *reinterpret_cast<float4*>(out + (size_t)t * M3 + e) = make_float4(s[0], s[1], s[2], s[3]);
    }
}

// ---------------------------------------------------------------------------
extern "C" void kernel_launch(void* const* d_in, const int* in_sizes, int n_in,
                              void* d_out, int out_size) {
    const float* x     = (const float*)d_in[0];
    const float* W     = (const float*)d_in[1];
    const float* gamma = (const float*)d_in[2];
    const float* beta  = (const float*)d_in[3];
    float* out = (float*)d_out;

    dim3 gemm_grid(DOUT / 128, MROWS / 128);     // (4, 512)
    sgemm_kernel<<<gemm_grid, 256>>>(x, W);
    reduce_stats_kernel<<<RED_BLOCKS, 256>>>();
    finalize_stats_kernel<<<16, 32>>>();
    lif_kernel<<<M3 / (256 * 4), 256>>>(gamma, beta, out);
}

// round 14
// speedup vs baseline: 1.6107x; 1.6107x over previous
#include <cuda_runtime.h>
#include <math.h>

// Problem dims (fixed per reference setup_inputs)
#define TT   4
#define BBB  64
#define NNN  256
#define DIN  512
#define DOUT 512
#define MROWS (TT * BBB * NNN)        // 65536 rows total
#define M3   (BBB * NNN * DOUT)       // 8388608 elems per time step
#define RED_ROWS 256
#define RED_BLOCKS (MROWS / RED_ROWS) // 256
#define BK 16
#define NCHUNKS (DIN / BK)            // 32

// Scratch (allocation-free: __device__ globals)
__device__ float g_z[(size_t)MROWS * DOUT];
__device__ float g_psum[RED_BLOCKS * DOUT];
__device__ float g_psumsq[RED_BLOCKS * DOUT];
__device__ float g_mean[DOUT];
__device__ float g_rstd[DOUT];

// ---------------------------------------------------------------------------
// SGEMM: Z[m,o] = sum_d X[m,d] * W[o,d]
// VERBATIM round-5 kernel (best measured GEMM): 128x128 CTA tile, BK=16,
// 256 threads, 8x8/thread, double-buffered SMEM, 2 CTAs/SM. Single fp32
// accumulator per element, k = 0..511 ascending -> bit-identical output.
// ---------------------------------------------------------------------------
__global__ __launch_bounds__(256, 2) void sgemm_kernel(const float* __restrict__ X,
                                                       const float* __restrict__ W) {
    __shared__ __align__(16) float As[2][BK][128];
    __shared__ __align__(16) float Bs[2][BK][128];

    const int tid = threadIdx.x;
    const int tx = tid & 15;          // column groups
    const int ty = tid >> 4;          // row groups
    const int r0 = tid >> 2;          // load row (first half)
    const int q0 = tid & 3;           // float4 index within 16-float row chunk

    const float* Ab = X + (size_t)blockIdx.y * 128 * DIN;
    const float* Wb = W + (size_t)blockIdx.x * 128 * DIN;

    float acc[8][8];
#pragma unroll
    for (int i = 0; i < 8; i++)
#pragma unroll
        for (int j = 0; j < 8; j++) acc[i][j] = 0.f;

    float4 ra0, ra1, rb0, rb1;   // staging regs for the in-flight chunk

    // --- prologue: chunk 0 -> buf 0
    ra0 = *reinterpret_cast<const float4*>(Ab + (size_t)r0 * DIN + q0 * 4);
    ra1 = *reinterpret_cast<const float4*>(Ab + (size_t)(r0 + 64) * DIN + q0 * 4);
    rb0 = *reinterpret_cast<const float4*>(Wb + (size_t)r0 * DIN + q0 * 4);
    rb1 = *reinterpret_cast<const float4*>(Wb + (size_t)(r0 + 64) * DIN + q0 * 4);
    {
        float a0[4] = {ra0.x, ra0.y, ra0.z, ra0.w};
        float a1[4] = {ra1.x, ra1.y, ra1.z, ra1.w};
        float b0[4] = {rb0.x, rb0.y, rb0.z, rb0.w};
        float b1[4] = {rb1.x, rb1.y, rb1.z, rb1.w};
#pragma unroll
        for (int u = 0; u < 4; u++) {
            As[0][q0 * 4 + u][r0]      = a0[u];
            As[0][q0 * 4 + u][r0 + 64] = a1[u];
            Bs[0][q0 * 4 + u][r0]      = b0[u];
            Bs[0][q0 * 4 + u][r0 + 64] = b1[u];
        }
    }
    __syncthreads();

    // LDG chunk 1
    ra0 = *reinterpret_cast<const float4*>(Ab + (size_t)r0 * DIN + BK + q0 * 4);
    ra1 = *reinterpret_cast<const float4*>(Ab + (size_t)(r0 + 64) * DIN + BK + q0 * 4);
    rb0 = *reinterpret_cast<const float4*>(Wb + (size_t)r0 * DIN + BK + q0 * 4);
    rb1 = *reinterpret_cast<const float4*>(Wb + (size_t)(r0 + 64) * DIN + BK + q0 * 4);

    for (int c = 0; c < NCHUNKS; c++) {
        const int cur = c & 1;
        if (c + 1 < NCHUNKS) {
            const int nxt = cur ^ 1;
            float a0[4] = {ra0.x, ra0.y, ra0.z, ra0.w};
            float a1[4] = {ra1.x, ra1.y, ra1.z, ra1.w};
            float b0[4] = {rb0.x, rb0.y, rb0.z, rb0.w};
            float b1[4] = {rb1.x, rb1.y, rb1.z, rb1.w};
#pragma unroll
            for (int u = 0; u < 4; u++) {
                As[nxt][q0 * 4 + u][r0]      = a0[u];
                As[nxt][q0 * 4 + u][r0 + 64] = a1[u];
                Bs[nxt][q0 * 4 + u][r0]      = b0[u];
                Bs[nxt][q0 * 4 + u][r0 + 64] = b1[u];
            }
        }
        if (c + 2 < NCHUNKS) {
            const int k0 = (c + 2) * BK;
            ra0 = *reinterpret_cast<const float4*>(Ab + (size_t)r0 * DIN + k0 + q0 * 4);
            ra1 = *reinterpret_cast<const float4*>(Ab + (size_t)(r0 + 64) * DIN + k0 + q0 * 4);
            rb0 = *reinterpret_cast<const float4*>(Wb + (size_t)r0 * DIN + k0 + q0 * 4);
            rb1 = *reinterpret_cast<const float4*>(Wb + (size_t)(r0 + 64) * DIN + k0 + q0 * 4);
        }
        // Compute chunk c: k ascending (bit-identical order)
#pragma unroll
        for (int kk = 0; kk < BK; kk++) {
            float4 a0 = *reinterpret_cast<const float4*>(&As[cur][kk][ty * 4]);
            float4 a1 = *reinterpret_cast<const float4*>(&As[cur][kk][64 + ty * 4]);
            float4 b0 = *reinterpret_cast<const float4*>(&Bs[cur][kk][tx * 4]);
            float4 b1 = *reinterpret_cast<const float4*>(&Bs[cur][kk][64 + tx * 4]);
            float ra[8] = {a0.x, a0.y, a0.z, a0.w, a1.x, a1.y, a1.z, a1.w};
            float rb[8] = {b0.x, b0.y, b0.z, b0.w, b1.x, b1.y, b1.z, b1.w};
#pragma unroll
            for (int i = 0; i < 8; i++)
#pragma unroll
                for (int j = 0; j < 8; j++) acc[i][j] += ra[i] * rb[j];
        }
        __syncthreads();
    }

    // Epilogue (same mapping as round 5)
#pragma unroll
    for (int rh = 0; rh < 2; rh++)
#pragma unroll
        for (int i = 0; i < 4; i++) {
            int row = blockIdx.y * 128 + rh * 64 + ty * 4 + i;
            float* zrow = g_z + (size_t)row * DOUT + blockIdx.x * 128;
#pragma unroll
            for (int ch = 0; ch < 2; ch++) {
                float4 v;
                v.x = acc[rh * 4 + i][ch * 4 + 0];
                v.y = acc[rh * 4 + i][ch * 4 + 1];
                v.z = acc[rh * 4 + i][ch * 4 + 2];
                v.w = acc[rh * 4 + i][ch * 4 + 3];
                *reinterpret_cast<float4*>(zrow + ch * 64 + tx * 4) = v;
            }
        }
}

// ---------------------------------------------------------------------------
// Stats: stage-1 verbatim; finalize parallel (16 CTAs x 32 thr, batched loads,
// add order b = 0..255 ascending -> bit-identical). Validated in round 11.
// ---------------------------------------------------------------------------
__global__ __launch_bounds__(256) void reduce_stats_kernel() {
    const int c = threadIdx.x;
    const size_t base = (size_t)blockIdx.x * RED_ROWS * DOUT;
    float s0 = 0.f, q0 = 0.f, s1 = 0.f, q1 = 0.f;
    for (int r = 0; r < RED_ROWS; r++) {
        float z0 = g_z[base + (size_t)r * DOUT + c];
        float z1 = g_z[base + (size_t)r * DOUT + c + 256];
        s0 += z0; q0 += z0 * z0;
        s1 += z1; q1 += z1 * z1;
    }
    g_psum  [blockIdx.x * DOUT + c]       = s0;
    g_psumsq[blockIdx.x * DOUT + c]       = q0;
    g_psum  [blockIdx.x * DOUT + c + 256] = s1;
    g_psumsq[blockIdx.x * DOUT + c + 256] = q1;
}

__global__ void finalize_stats_kernel() {
    const int o = blockIdx.x * 32 + threadIdx.x;   // one channel per thread
    float s = 0.f, q = 0.f;
    for (int b0 = 0; b0 < RED_BLOCKS; b0 += 8) {
        float sv[8], qv[8];
#pragma unroll
        for (int u = 0; u < 8; u++) {
            sv[u] = g_psum  [(b0 + u) * DOUT + o];
            qv[u] = g_psumsq[(b0 + u) * DOUT + o];
        }
#pragma unroll
        for (int u = 0; u < 8; u++) {   // add order: b ascending (bit-identical)
            s += sv[u];
            q += qv[u];
        }
    }
    const float invM = 1.0f / (float)MROWS;
    float mean = s * invM;
    float var = q * invM - mean * mean;
    g_mean[o] = mean;
    g_rstd[o] = 1.0f / sqrtf(var + 1e-5f);
}

// ---------------------------------------------------------------------------
// LIF: verbatim from the passing kernels.
// ---------------------------------------------------------------------------
__global__ __launch_bounds__(256) void lif_kernel(const float* __restrict__ gamma,
                                                  const float* __restrict__ beta,
                                                  float* __restrict__ out) {
    size_t e = ((size_t)blockIdx.x * blockDim.x + threadIdx.x) * 4;
    int o = (int)(e & (DOUT - 1));

    float4 mn4 = *reinterpret_cast<const float4*>(g_mean + o);
    float4 rs4 = *reinterpret_cast<const float4*>(g_rstd + o);
    float4 gm4 = *reinterpret_cast<const float4*>(gamma + o);
    float4 bt4 = *reinterpret_cast<const float4*>(beta + o);
    float mn[4] = {mn4.x, mn4.y, mn4.z, mn4.w};
    float rs[4] = {rs4.x, rs4.y, rs4.z, rs4.w};
    float gm[4] = {gm4.x, gm4.y, gm4.z, gm4.w};
    float bt[4] = {bt4.x, bt4.y, bt4.z, bt4.w};

    float v[4] = {0.f, 0.f, 0.f, 0.f};
#pragma unroll
    for (int t = 0; t < TT; t++) {
        float4 z4 = *reinterpret_cast<const float4*>(g_z + (size_t)t * M3 + e);
        float z[4] = {z4.x, z4.y, z4.z, z4.w};
        float s[4];
#pragma unroll
        for (int l = 0; l < 4; l++) {
            float zn = __fadd_rn(__fmul_rn(__fmul_rn(__fsub_rn(z[l], mn[l]), rs[l]), gm[l]), bt[l]);
            v[l] = __fadd_rn(v[l], __fmul_rn(__fsub_rn(zn, v[l]), 0.5f));
            bool fire = (v[l] >= 1.0f);
            s[l] = fire ? 1.0f : 0.0f;
            v[l] = fire ? 0.0f : v[l];
        }
        *reinterpret_cast<float4*>(out + (size_t)t * M3 + e) = make_float4(s[0], s[1], s[2], s[3]);
    }
}

// ---------------------------------------------------------------------------
extern "C" void kernel_launch(void* const* d_in, const int* in_sizes, int n_in,
                              void* d_out, int out_size) {
    const float* x     = (const float*)d_in[0];
    const float* W     = (const float*)d_in[1];
    const float* gamma = (const float*)d_in[2];
    const float* beta  = (const float*)d_in[3];
    float* out = (float*)d_out;

    dim3 gemm_grid(DOUT / 128, MROWS / 128);     // (4, 512)
    sgemm_kernel<<<gemm_grid, 256>>>(x, W);
    reduce_stats_kernel<<<RED_BLOCKS, 256>>>();
    finalize_stats_kernel<<<16, 32>>>();
    lif_kernel<<<M3 / (256 * 4), 256>>>(gamma, beta, out);
}